// round 15
// baseline (speedup 1.0000x reference)
#include <cuda_runtime.h>
#include <cstdint>

#define BB 64
#define NN 8192
#define WW 64
#define EPSF 1e-8f
#define NCB 8             // chunks (blocks) per batch
#define RB 1024           // rows per block
#define NSLAB (RB / 256)  // 4

typedef unsigned long long ull;

// ---------------- scratch (device globals; no allocation allowed) ----------------
__device__ __align__(16) float4 g_parte4[BB * NCB];        // per-chunk e sums (per head)
__device__ __align__(16) float4 g_partw4[BB * NCB];        // per-chunk w sums (per head)
__device__ __align__(16) float4 g_parto4[BB * NCB * 64];   // per-chunk output partials
__device__ __align__(16) float4 g_edge[BB][NCB][2];        // boundary e rows [first,last]
__device__ int g_c1[BB];                                   // phase-A arrival counters
__device__ int g_c2[BB];                                   // phase-C arrival counters

__device__ __forceinline__ float softplusf(float x) {
    return (x > 20.f) ? x : log1pf(expf(x));
}
__device__ __forceinline__ ull pk2(float lo, float hi) {
    ull r; asm("mov.b64 %0, {%1, %2};" : "=l"(r) : "f"(lo), "f"(hi)); return r;
}
__device__ __forceinline__ void upk2(ull v, float& lo, float& hi) {
    asm("mov.b64 {%0, %1}, %2;" : "=f"(lo), "=f"(hi) : "l"(v));
}
__device__ __forceinline__ ull ffma2(ull a, ull b, ull c) {
    ull d; asm("fma.rn.f32x2 %0, %1, %2, %3;" : "=l"(d) : "l"(a), "l"(b), "l"(c)); return d;
}

// =====================================================================
// Fused kernel: scores -> (per-batch spin sync) -> weights -> read -> out.
// grid (NCB, BB) = 512 blocks, 256 threads, 3 blocks/SM (84-reg cap).
// Phase A: R12's 8-lane-per-row layout (3.75 warp-shfl/row), unroll 4
// to bound the in-flight-load register batch under the 84-reg budget.
// =====================================================================
__global__ void __launch_bounds__(256, 3) k_fused(const float* __restrict__ mem,
                                                  const float* __restrict__ ctrl,
                                                  const float* __restrict__ prev,
                                                  float* __restrict__ out) {
    __shared__ float4 s_buf[RB];        // e (A/B), then w (C), then reduction  (16KB)
    __shared__ float4 s_dot[256];       // per-slab dots (4KB)
    __shared__ float  s_nm[256];        // per-slab norms (1KB)
    __shared__ float  s_keys[256];
    __shared__ float  s_nk[4], s_beta[4];
    __shared__ float4 s_scA[4], s_scB[4];
    __shared__ float4 s_pw[8];
    __shared__ float4 s_einv, s_winv;
    __shared__ int    s_last;

    const int t    = threadIdx.x;
    const int lane = t & 31;
    const int wid  = t >> 5;
    const int cc   = lane & 7;          // 16B chunk id within row half
    const int rq   = lane >> 3;         // row within warp quad
    const int c    = blockIdx.x;        // chunk 0..7
    const int b    = blockIdx.y;
    const float* cb = ctrl + b * 280;

    // ---- prep: keys + per-head scalars ----
    s_keys[t] = tanhf(cb[t]);
    __syncthreads();
    if (t < 4) {
        const float* kk = s_keys + t * 64;
        float s = 0.f;
        #pragma unroll
        for (int w = 0; w < 64; w++) s = fmaf(kk[w], kk[w], s);
        s_nk[t]   = sqrtf(s);
        s_beta[t] = softplusf(cb[256 + t]);
        float gate  = 1.f / (1.f + expf(-cb[260 + t]));
        float gamma = 1.f + softplusf(cb[276 + t]);
        float a0 = cb[264 + t * 3], a1 = cb[265 + t * 3], a2 = cb[266 + t * 3];
        float mx = fmaxf(a0, fmaxf(a1, a2));
        float e0 = expf(a0 - mx), e1 = expf(a1 - mx), e2 = expf(a2 - mx);
        float inv3 = 1.f / (e0 + e1 + e2);
        s_scA[t] = make_float4(gate, gamma, 0.f, 0.f);
        s_scB[t] = make_float4(e0 * inv3, e1 * inv3, e2 * inv3, 0.f);
    }
    __syncthreads();

    // keys for chunks (j*8 + cc), j=0,1, all 4 heads -> 16 ull regs
    ull kk[4][2][2];
    #pragma unroll
    for (int h = 0; h < 4; h++)
        #pragma unroll
        for (int j = 0; j < 2; j++) {
            float4 kv = *(const float4*)(s_keys + h * 64 + j * 32 + cc * 4);
            kk[h][j][0] = pk2(kv.x, kv.y); kk[h][j][1] = pk2(kv.z, kv.w);
        }

    const float4* mem4 = (const float4*)mem + ((size_t)b * NN + (size_t)c * RB) * 16;

    // ================= Phase A: scores, e -> s_buf =================
    float4 esum = make_float4(0.f, 0.f, 0.f, 0.f);
    for (int slab = 0; slab < NSLAB; slab++) {
        #pragma unroll 4
        for (int it = 0; it < 8; it++) {
            const int rs = it * 32 + wid * 4 + rq;        // row within slab 0..255
            const int rl = slab * 256 + rs;
            float4 m0 = mem4[rl * 16 + cc];
            float4 m1 = mem4[rl * 16 + 8 + cc];
            ull p0 = pk2(m0.x, m0.y), p1 = pk2(m0.z, m0.w);
            ull p2 = pk2(m1.x, m1.y), p3 = pk2(m1.z, m1.w);

            ull nm = ffma2(p0, p0, 0ull); nm = ffma2(p1, p1, nm);
            nm = ffma2(p2, p2, nm);       nm = ffma2(p3, p3, nm);
            ull d0 = ffma2(p0, kk[0][0][0], 0ull); d0 = ffma2(p1, kk[0][0][1], d0);
            d0 = ffma2(p2, kk[0][1][0], d0);       d0 = ffma2(p3, kk[0][1][1], d0);
            ull d1 = ffma2(p0, kk[1][0][0], 0ull); d1 = ffma2(p1, kk[1][0][1], d1);
            d1 = ffma2(p2, kk[1][1][0], d1);       d1 = ffma2(p3, kk[1][1][1], d1);
            ull d2 = ffma2(p0, kk[2][0][0], 0ull); d2 = ffma2(p1, kk[2][0][1], d2);
            d2 = ffma2(p2, kk[2][1][0], d2);       d2 = ffma2(p3, kk[2][1][1], d2);
            ull d3 = ffma2(p0, kk[3][0][0], 0ull); d3 = ffma2(p1, kk[3][0][1], d3);
            d3 = ffma2(p2, kk[3][1][0], d3);       d3 = ffma2(p3, kk[3][1][1], d3);

            float lo, hi;
            upk2(nm, lo, hi); float vn = lo + hi;
            upk2(d0, lo, hi); float v0 = lo + hi;
            upk2(d1, lo, hi); float v1 = lo + hi;
            upk2(d2, lo, hi); float v2 = lo + hi;
            upk2(d3, lo, hi); float v3 = lo + hi;
            #pragma unroll
            for (int s = 1; s <= 4; s <<= 1) {            // 8-lane butterfly
                vn += __shfl_xor_sync(0xffffffffu, vn, s);
                v0 += __shfl_xor_sync(0xffffffffu, v0, s);
                v1 += __shfl_xor_sync(0xffffffffu, v1, s);
                v2 += __shfl_xor_sync(0xffffffffu, v2, s);
                v3 += __shfl_xor_sync(0xffffffffu, v3, s);
            }
            if (cc == 0) {
                s_dot[rs] = make_float4(v0, v1, v2, v3);
                s_nm[rs]  = vn;
            }
        }
        __syncthreads();
        {   // slab epilogue: all 256 threads, one row each (MUFU spread)
            float4 d  = s_dot[t];
            float nmr = sqrtf(s_nm[t]);
            float4 e;
            e.x = __expf(s_beta[0] * (__fdividef(d.x, nmr * s_nk[0] + EPSF) - 1.f));
            e.y = __expf(s_beta[1] * (__fdividef(d.y, nmr * s_nk[1] + EPSF) - 1.f));
            e.z = __expf(s_beta[2] * (__fdividef(d.z, nmr * s_nk[2] + EPSF) - 1.f));
            e.w = __expf(s_beta[3] * (__fdividef(d.w, nmr * s_nk[3] + EPSF) - 1.f));
            s_buf[slab * 256 + t] = e;
            esum.x += e.x; esum.y += e.y; esum.z += e.z; esum.w += e.w;
        }
        __syncthreads();
    }

    // block e-sum reduction
    #pragma unroll
    for (int s = 16; s > 0; s >>= 1) {
        esum.x += __shfl_xor_sync(0xffffffffu, esum.x, s);
        esum.y += __shfl_xor_sync(0xffffffffu, esum.y, s);
        esum.z += __shfl_xor_sync(0xffffffffu, esum.z, s);
        esum.w += __shfl_xor_sync(0xffffffffu, esum.w, s);
    }
    if (lane == 0) s_pw[wid] = esum;
    __syncthreads();

    // ---- sync 1: publish e-sum + edges, spin until batch complete ----
    if (t == 0) {
        float4 a = s_pw[0];
        #pragma unroll
        for (int i = 1; i < 8; i++) {
            float4 q = s_pw[i];
            a.x += q.x; a.y += q.y; a.z += q.z; a.w += q.w;
        }
        g_parte4[b * NCB + c] = a;
        g_edge[b][c][0] = s_buf[0];
        g_edge[b][c][1] = s_buf[RB - 1];
        __threadfence();                       // release (t0 performed all these stores)
        atomicAdd(&g_c1[b], 1);
        while (*((volatile int*)&g_c1[b]) < NCB) __nanosleep(32);
        __threadfence();                       // acquire
        float4 a4 = make_float4(0.f, 0.f, 0.f, 0.f);
        #pragma unroll
        for (int i = 0; i < NCB; i++) {
            float4 p = g_parte4[b * NCB + i];
            a4.x += p.x; a4.y += p.y; a4.z += p.z; a4.w += p.w;
        }
        s_einv.x = 1.f / a4.x; s_einv.y = 1.f / a4.y;
        s_einv.z = 1.f / a4.z; s_einv.w = 1.f / a4.w;
    }
    __syncthreads();

    // ================= Phase B: weights (registers), then overwrite s_buf =================
    float4 wreg[NSLAB];
    {
        float4 wacc = make_float4(0.f, 0.f, 0.f, 0.f);
        const float4 edgeL = g_edge[b][(c + NCB - 1) & (NCB - 1)][1];
        const float4 edgeR = g_edge[b][(c + 1) & (NCB - 1)][0];
        const float4 ei4 = s_einv;
        #pragma unroll
        for (int j = 0; j < NSLAB; j++) {
            const int r = j * 256 + t;
            const int n = c * RB + r;
            const int nmi = (n - 1) & (NN - 1);
            const int npi = (n + 1) & (NN - 1);
            float4 ec = s_buf[r];
            float4 em = (r == 0)      ? edgeL : s_buf[r - 1];
            float4 ep = (r == RB - 1) ? edgeR : s_buf[r + 1];
            float emv[4] = {em.x, em.y, em.z, em.w};
            float ecv[4] = {ec.x, ec.y, ec.z, ec.w};
            float epv[4] = {ep.x, ep.y, ep.z, ep.w};
            float eiv[4] = {ei4.x, ei4.y, ei4.z, ei4.w};
            float ws[4];
            #pragma unroll
            for (int h = 0; h < 4; h++) {
                float4 A  = s_scA[h];
                float4 Bv = s_scB[h];
                float gg  = A.x, om = 1.f - gg;
                const float* pb = prev + ((size_t)b * 4 + h) * NN;
                float wim = fmaf(gg, emv[h] * eiv[h], om * pb[nmi]);
                float wic = fmaf(gg, ecv[h] * eiv[h], om * pb[n]);
                float wip = fmaf(gg, epv[h] * eiv[h], om * pb[npi]);
                float wsf = Bv.x * wim + Bv.y * wic + Bv.z * wip;
                ws[h] = __powf(wsf, A.y);       // wsf > 0 always
            }
            wreg[j] = make_float4(ws[0], ws[1], ws[2], ws[3]);
            wacc.x += ws[0]; wacc.y += ws[1]; wacc.z += ws[2]; wacc.w += ws[3];
        }
        __syncthreads();                        // all e reads done
        #pragma unroll
        for (int j = 0; j < NSLAB; j++) s_buf[j * 256 + t] = wreg[j];

        #pragma unroll
        for (int s = 16; s > 0; s >>= 1) {
            wacc.x += __shfl_xor_sync(0xffffffffu, wacc.x, s);
            wacc.y += __shfl_xor_sync(0xffffffffu, wacc.y, s);
            wacc.z += __shfl_xor_sync(0xffffffffu, wacc.z, s);
            wacc.w += __shfl_xor_sync(0xffffffffu, wacc.w, s);
        }
        if (lane == 0) s_pw[wid] = wacc;
    }
    __syncthreads();
    if (t == 0) {
        float4 a = s_pw[0];
        #pragma unroll
        for (int i = 1; i < 8; i++) {
            float4 q = s_pw[i];
            a.x += q.x; a.y += q.y; a.z += q.z; a.w += q.w;
        }
        g_partw4[b * NCB + c] = a;              // fenced before c2 add
    }

    // ================= Phase C: read pass, accumulate =================
    const int rsub = t >> 4;
    const int w4   = t & 15;
    const float4* basec = mem4 + w4;

    ull a00 = 0, a01 = 0, a10 = 0, a11 = 0, a20 = 0, a21 = 0, a30 = 0, a31 = 0;
    #pragma unroll 4
    for (int k = 0; k < RB / 16; k++) {
        const int r = k * 16 + rsub;
        float4 m  = basec[r * 16];
        float4 wv = s_buf[r];                   // 2-address broadcast per warp
        ull w0 = pk2(wv.x, wv.x), w1 = pk2(wv.y, wv.y);
        ull w2 = pk2(wv.z, wv.z), w3 = pk2(wv.w, wv.w);
        ull m01 = pk2(m.x, m.y), m23 = pk2(m.z, m.w);
        a00 = ffma2(w0, m01, a00); a01 = ffma2(w0, m23, a01);
        a10 = ffma2(w1, m01, a10); a11 = ffma2(w1, m23, a11);
        a20 = ffma2(w2, m01, a20); a21 = ffma2(w2, m23, a21);
        a30 = ffma2(w3, m01, a30); a31 = ffma2(w3, m23, a31);
    }

    __syncthreads();                            // w consumed; reuse s_buf as reduction buf
    {
        ulonglong2 q;
        q.x = a00; q.y = a01; *(ulonglong2*)&s_buf[(rsub * 4 + 0) * 16 + w4] = q;
        q.x = a10; q.y = a11; *(ulonglong2*)&s_buf[(rsub * 4 + 1) * 16 + w4] = q;
        q.x = a20; q.y = a21; *(ulonglong2*)&s_buf[(rsub * 4 + 2) * 16 + w4] = q;
        q.x = a30; q.y = a31; *(ulonglong2*)&s_buf[(rsub * 4 + 3) * 16 + w4] = q;
    }
    __syncthreads();
    if (t < 64) {
        const int h = t >> 4, w = t & 15;
        float4 acc = s_buf[(0 * 4 + h) * 16 + w];
        #pragma unroll
        for (int k = 1; k < 16; k++) {
            float4 a = s_buf[(k * 4 + h) * 16 + w];
            acc.x += a.x; acc.y += a.y; acc.z += a.z; acc.w += a.w;
        }
        g_parto4[(b * NCB + c) * 64 + t] = acc;
        __threadfence();                        // release (storing threads only)
    }
    __syncthreads();

    // ---- sync 2: last block of batch reduces + writes out ----
    if (t == 0) {
        __threadfence();                        // release for t0's g_partw store
        int old = atomicAdd(&g_c2[b], 1);
        s_last = (old == NCB - 1) ? 1 : 0;
    }
    __syncthreads();
    if (s_last) {
        if (t == 0) {
            __threadfence();                    // acquire
            float4 a4 = make_float4(EPSF, EPSF, EPSF, EPSF);
            #pragma unroll
            for (int i = 0; i < NCB; i++) {
                float4 q = g_partw4[b * NCB + i];
                a4.x += q.x; a4.y += q.y; a4.z += q.z; a4.w += q.w;
            }
            s_winv.x = 1.f / a4.x; s_winv.y = 1.f / a4.y;
            s_winv.z = 1.f / a4.z; s_winv.w = 1.f / a4.w;
        }
        __syncthreads();
        if (t < 64) {
            float4 r = make_float4(0.f, 0.f, 0.f, 0.f);
            #pragma unroll
            for (int i = 0; i < NCB; i++) {
                float4 a = g_parto4[(b * NCB + i) * 64 + t];
                r.x += a.x; r.y += a.y; r.z += a.z; r.w += a.w;
            }
            float inv = (t < 16) ? s_winv.x : (t < 32) ? s_winv.y
                      : (t < 48) ? s_winv.z : s_winv.w;
            r.x *= inv; r.y *= inv; r.z *= inv; r.w *= inv;
            *(((float4*)out) + b * 64 + t) = r;
        }
        if (t == 0) {                           // reset counters for next replay
            g_c1[b] = 0;
            g_c2[b] = 0;
        }
    }
}

// =====================================================================
extern "C" void kernel_launch(void* const* d_in, const int* in_sizes, int n_in,
                              void* d_out, int out_size) {
    const float* mem  = nullptr;
    const float* ctrl = nullptr;
    const float* prev = nullptr;
    for (int i = 0; i < n_in; i++) {
        if (in_sizes[i] == BB * NN * WW)     mem  = (const float*)d_in[i];
        else if (in_sizes[i] == BB * 280)    ctrl = (const float*)d_in[i];
        else if (in_sizes[i] == BB * 4 * NN) prev = (const float*)d_in[i];
    }

    dim3 grid(NCB, BB);
    k_fused<<<grid, 256>>>(mem, ctrl, prev, (float*)d_out);
}

// round 16
// speedup vs baseline: 1.1445x; 1.1445x over previous
#include <cuda_runtime.h>
#include <cstdint>

#define BB 64
#define NN 8192
#define WW 64
#define EPSF 1e-8f
#define NCB 16            // chunks (blocks) per batch
#define RB 512            // rows per block
#define NSLAB (RB / 256)  // 2

typedef unsigned long long ull;

// ---------------- scratch (device globals; no allocation allowed) ----------------
__device__ __align__(16) float4 g_parte4[BB * NCB];        // per-chunk e sums (per head)
__device__ __align__(16) float4 g_partw4[BB * NCB];        // per-chunk w sums (per head)
__device__ __align__(16) float4 g_parto4[BB * NCB * 64];   // per-chunk output partials
__device__ __align__(16) float4 g_edge[BB][NCB][2];        // boundary e rows [first,last]
__device__ int g_c1[BB];                                   // phase-A arrival counters
__device__ int g_c2[BB];                                   // phase-C arrival counters

__device__ __forceinline__ float softplusf(float x) {
    return (x > 20.f) ? x : log1pf(expf(x));
}
__device__ __forceinline__ ull pk2(float lo, float hi) {
    ull r; asm("mov.b64 %0, {%1, %2};" : "=l"(r) : "f"(lo), "f"(hi)); return r;
}
__device__ __forceinline__ void upk2(ull v, float& lo, float& hi) {
    asm("mov.b64 {%0, %1}, %2;" : "=f"(lo), "=f"(hi) : "l"(v));
}
__device__ __forceinline__ ull ffma2(ull a, ull b, ull c) {
    ull d; asm("fma.rn.f32x2 %0, %1, %2, %3;" : "=l"(d) : "l"(a), "l"(b), "l"(c)); return d;
}

// =====================================================================
// Fused kernel: scores -> (per-batch spin sync) -> weights -> read -> out.
// grid (NCB, BB) = 1024 blocks, 256 threads, 2 blocks/SM (R12 config).
// RB=512: per-block working set 128KB -> co-resident set ~38MB, deep L2 fit.
// =====================================================================
__global__ void __launch_bounds__(256, 2) k_fused(const float* __restrict__ mem,
                                                  const float* __restrict__ ctrl,
                                                  const float* __restrict__ prev,
                                                  float* __restrict__ out) {
    __shared__ float4 s_buf[1024];      // e/w in first RB entries; 1024 for reduction (16KB)
    __shared__ float4 s_dot[256];       // per-slab dots (4KB)
    __shared__ float  s_nm[256];        // per-slab norms (1KB)
    __shared__ float  s_keys[256];
    __shared__ float  s_nk[4], s_beta[4];
    __shared__ float4 s_scA[4], s_scB[4];
    __shared__ float4 s_pw[8];
    __shared__ float4 s_einv, s_winv;
    __shared__ int    s_last;

    const int t    = threadIdx.x;
    const int lane = t & 31;
    const int wid  = t >> 5;
    const int cc   = lane & 7;          // 16B chunk id within row half
    const int rq   = lane >> 3;         // row within warp quad
    const int c    = blockIdx.x;        // chunk 0..15
    const int b    = blockIdx.y;
    const float* cb = ctrl + b * 280;

    // ---- prep: keys + per-head scalars ----
    s_keys[t] = tanhf(cb[t]);
    __syncthreads();
    if (t < 4) {
        const float* kk = s_keys + t * 64;
        float s = 0.f;
        #pragma unroll
        for (int w = 0; w < 64; w++) s = fmaf(kk[w], kk[w], s);
        s_nk[t]   = sqrtf(s);
        s_beta[t] = softplusf(cb[256 + t]);
        float gate  = 1.f / (1.f + expf(-cb[260 + t]));
        float gamma = 1.f + softplusf(cb[276 + t]);
        float a0 = cb[264 + t * 3], a1 = cb[265 + t * 3], a2 = cb[266 + t * 3];
        float mx = fmaxf(a0, fmaxf(a1, a2));
        float e0 = expf(a0 - mx), e1 = expf(a1 - mx), e2 = expf(a2 - mx);
        float inv3 = 1.f / (e0 + e1 + e2);
        s_scA[t] = make_float4(gate, gamma, 0.f, 0.f);
        s_scB[t] = make_float4(e0 * inv3, e1 * inv3, e2 * inv3, 0.f);
    }
    __syncthreads();

    // keys for chunks (j*8 + cc), j=0,1, all 4 heads -> 16 ull regs
    ull kk[4][2][2];
    #pragma unroll
    for (int h = 0; h < 4; h++)
        #pragma unroll
        for (int j = 0; j < 2; j++) {
            float4 kv = *(const float4*)(s_keys + h * 64 + j * 32 + cc * 4);
            kk[h][j][0] = pk2(kv.x, kv.y); kk[h][j][1] = pk2(kv.z, kv.w);
        }

    const float4* mem4 = (const float4*)mem + ((size_t)b * NN + (size_t)c * RB) * 16;

    // ================= Phase A: scores, e -> s_buf =================
    float4 esum = make_float4(0.f, 0.f, 0.f, 0.f);
    for (int slab = 0; slab < NSLAB; slab++) {
        #pragma unroll
        for (int it = 0; it < 8; it++) {
            const int rs = it * 32 + wid * 4 + rq;        // row within slab 0..255
            const int rl = slab * 256 + rs;
            float4 m0 = mem4[rl * 16 + cc];
            float4 m1 = mem4[rl * 16 + 8 + cc];
            ull p0 = pk2(m0.x, m0.y), p1 = pk2(m0.z, m0.w);
            ull p2 = pk2(m1.x, m1.y), p3 = pk2(m1.z, m1.w);

            ull nm = ffma2(p0, p0, 0ull); nm = ffma2(p1, p1, nm);
            nm = ffma2(p2, p2, nm);       nm = ffma2(p3, p3, nm);
            ull d0 = ffma2(p0, kk[0][0][0], 0ull); d0 = ffma2(p1, kk[0][0][1], d0);
            d0 = ffma2(p2, kk[0][1][0], d0);       d0 = ffma2(p3, kk[0][1][1], d0);
            ull d1 = ffma2(p0, kk[1][0][0], 0ull); d1 = ffma2(p1, kk[1][0][1], d1);
            d1 = ffma2(p2, kk[1][1][0], d1);       d1 = ffma2(p3, kk[1][1][1], d1);
            ull d2 = ffma2(p0, kk[2][0][0], 0ull); d2 = ffma2(p1, kk[2][0][1], d2);
            d2 = ffma2(p2, kk[2][1][0], d2);       d2 = ffma2(p3, kk[2][1][1], d2);
            ull d3 = ffma2(p0, kk[3][0][0], 0ull); d3 = ffma2(p1, kk[3][0][1], d3);
            d3 = ffma2(p2, kk[3][1][0], d3);       d3 = ffma2(p3, kk[3][1][1], d3);

            float lo, hi;
            upk2(nm, lo, hi); float vn = lo + hi;
            upk2(d0, lo, hi); float v0 = lo + hi;
            upk2(d1, lo, hi); float v1 = lo + hi;
            upk2(d2, lo, hi); float v2 = lo + hi;
            upk2(d3, lo, hi); float v3 = lo + hi;
            #pragma unroll
            for (int s = 1; s <= 4; s <<= 1) {            // 8-lane butterfly
                vn += __shfl_xor_sync(0xffffffffu, vn, s);
                v0 += __shfl_xor_sync(0xffffffffu, v0, s);
                v1 += __shfl_xor_sync(0xffffffffu, v1, s);
                v2 += __shfl_xor_sync(0xffffffffu, v2, s);
                v3 += __shfl_xor_sync(0xffffffffu, v3, s);
            }
            if (cc == 0) {
                s_dot[rs] = make_float4(v0, v1, v2, v3);
                s_nm[rs]  = vn;
            }
        }
        __syncthreads();
        {   // slab epilogue: all 256 threads, one row each (MUFU spread)
            float4 d  = s_dot[t];
            float nmr = sqrtf(s_nm[t]);
            float4 e;
            e.x = __expf(s_beta[0] * (__fdividef(d.x, nmr * s_nk[0] + EPSF) - 1.f));
            e.y = __expf(s_beta[1] * (__fdividef(d.y, nmr * s_nk[1] + EPSF) - 1.f));
            e.z = __expf(s_beta[2] * (__fdividef(d.z, nmr * s_nk[2] + EPSF) - 1.f));
            e.w = __expf(s_beta[3] * (__fdividef(d.w, nmr * s_nk[3] + EPSF) - 1.f));
            s_buf[slab * 256 + t] = e;
            esum.x += e.x; esum.y += e.y; esum.z += e.z; esum.w += e.w;
        }
        __syncthreads();
    }

    // block e-sum reduction
    #pragma unroll
    for (int s = 16; s > 0; s >>= 1) {
        esum.x += __shfl_xor_sync(0xffffffffu, esum.x, s);
        esum.y += __shfl_xor_sync(0xffffffffu, esum.y, s);
        esum.z += __shfl_xor_sync(0xffffffffu, esum.z, s);
        esum.w += __shfl_xor_sync(0xffffffffu, esum.w, s);
    }
    if (lane == 0) s_pw[wid] = esum;
    __syncthreads();

    // ---- sync 1: publish e-sum + edges, spin until batch complete ----
    if (t == 0) {
        float4 a = s_pw[0];
        #pragma unroll
        for (int i = 1; i < 8; i++) {
            float4 q = s_pw[i];
            a.x += q.x; a.y += q.y; a.z += q.z; a.w += q.w;
        }
        g_parte4[b * NCB + c] = a;
        g_edge[b][c][0] = s_buf[0];
        g_edge[b][c][1] = s_buf[RB - 1];
        __threadfence();                       // release (t0 performed all these stores)
        atomicAdd(&g_c1[b], 1);
        while (*((volatile int*)&g_c1[b]) < NCB) __nanosleep(32);
        __threadfence();                       // acquire
        float4 a4 = make_float4(0.f, 0.f, 0.f, 0.f);
        #pragma unroll
        for (int i = 0; i < NCB; i++) {
            float4 p = g_parte4[b * NCB + i];
            a4.x += p.x; a4.y += p.y; a4.z += p.z; a4.w += p.w;
        }
        s_einv.x = 1.f / a4.x; s_einv.y = 1.f / a4.y;
        s_einv.z = 1.f / a4.z; s_einv.w = 1.f / a4.w;
    }
    __syncthreads();

    // ================= Phase B: weights (registers), then overwrite s_buf =================
    float4 wreg[NSLAB];
    {
        float4 wacc = make_float4(0.f, 0.f, 0.f, 0.f);
        const float4 edgeL = g_edge[b][(c + NCB - 1) & (NCB - 1)][1];
        const float4 edgeR = g_edge[b][(c + 1) & (NCB - 1)][0];
        const float4 ei4 = s_einv;
        #pragma unroll
        for (int j = 0; j < NSLAB; j++) {
            const int r = j * 256 + t;
            const int n = c * RB + r;
            const int nmi = (n - 1) & (NN - 1);
            const int npi = (n + 1) & (NN - 1);
            float4 ec = s_buf[r];
            float4 em = (r == 0)      ? edgeL : s_buf[r - 1];
            float4 ep = (r == RB - 1) ? edgeR : s_buf[r + 1];
            float emv[4] = {em.x, em.y, em.z, em.w};
            float ecv[4] = {ec.x, ec.y, ec.z, ec.w};
            float epv[4] = {ep.x, ep.y, ep.z, ep.w};
            float eiv[4] = {ei4.x, ei4.y, ei4.z, ei4.w};
            float ws[4];
            #pragma unroll
            for (int h = 0; h < 4; h++) {
                float4 A  = s_scA[h];
                float4 Bv = s_scB[h];
                float gg  = A.x, om = 1.f - gg;
                const float* pb = prev + ((size_t)b * 4 + h) * NN;
                float wim = fmaf(gg, emv[h] * eiv[h], om * pb[nmi]);
                float wic = fmaf(gg, ecv[h] * eiv[h], om * pb[n]);
                float wip = fmaf(gg, epv[h] * eiv[h], om * pb[npi]);
                float wsf = Bv.x * wim + Bv.y * wic + Bv.z * wip;
                ws[h] = __powf(wsf, A.y);       // wsf > 0 always
            }
            wreg[j] = make_float4(ws[0], ws[1], ws[2], ws[3]);
            wacc.x += ws[0]; wacc.y += ws[1]; wacc.z += ws[2]; wacc.w += ws[3];
        }
        __syncthreads();                        // all e reads done
        #pragma unroll
        for (int j = 0; j < NSLAB; j++) s_buf[j * 256 + t] = wreg[j];

        #pragma unroll
        for (int s = 16; s > 0; s >>= 1) {
            wacc.x += __shfl_xor_sync(0xffffffffu, wacc.x, s);
            wacc.y += __shfl_xor_sync(0xffffffffu, wacc.y, s);
            wacc.z += __shfl_xor_sync(0xffffffffu, wacc.z, s);
            wacc.w += __shfl_xor_sync(0xffffffffu, wacc.w, s);
        }
        if (lane == 0) s_pw[wid] = wacc;
    }
    __syncthreads();
    if (t == 0) {
        float4 a = s_pw[0];
        #pragma unroll
        for (int i = 1; i < 8; i++) {
            float4 q = s_pw[i];
            a.x += q.x; a.y += q.y; a.z += q.z; a.w += q.w;
        }
        g_partw4[b * NCB + c] = a;              // fenced before c2 add
    }

    // ================= Phase C: read pass (L2-hot), accumulate =================
    const int rsub = t >> 4;
    const int w4   = t & 15;
    const float4* basec = mem4 + w4;

    ull a00 = 0, a01 = 0, a10 = 0, a11 = 0, a20 = 0, a21 = 0, a30 = 0, a31 = 0;
    #pragma unroll 8
    for (int k = 0; k < RB / 16; k++) {
        const int r = k * 16 + rsub;
        float4 m  = basec[r * 16];
        float4 wv = s_buf[r];                   // 2-address broadcast per warp
        ull w0 = pk2(wv.x, wv.x), w1 = pk2(wv.y, wv.y);
        ull w2 = pk2(wv.z, wv.z), w3 = pk2(wv.w, wv.w);
        ull m01 = pk2(m.x, m.y), m23 = pk2(m.z, m.w);
        a00 = ffma2(w0, m01, a00); a01 = ffma2(w0, m23, a01);
        a10 = ffma2(w1, m01, a10); a11 = ffma2(w1, m23, a11);
        a20 = ffma2(w2, m01, a20); a21 = ffma2(w2, m23, a21);
        a30 = ffma2(w3, m01, a30); a31 = ffma2(w3, m23, a31);
    }

    __syncthreads();                            // w consumed; reuse s_buf as reduction buf
    {
        ulonglong2 q;
        q.x = a00; q.y = a01; *(ulonglong2*)&s_buf[(rsub * 4 + 0) * 16 + w4] = q;
        q.x = a10; q.y = a11; *(ulonglong2*)&s_buf[(rsub * 4 + 1) * 16 + w4] = q;
        q.x = a20; q.y = a21; *(ulonglong2*)&s_buf[(rsub * 4 + 2) * 16 + w4] = q;
        q.x = a30; q.y = a31; *(ulonglong2*)&s_buf[(rsub * 4 + 3) * 16 + w4] = q;
    }
    __syncthreads();
    if (t < 64) {
        const int h = t >> 4, w = t & 15;
        float4 acc = s_buf[(0 * 4 + h) * 16 + w];
        #pragma unroll
        for (int k = 1; k < 16; k++) {
            float4 a = s_buf[(k * 4 + h) * 16 + w];
            acc.x += a.x; acc.y += a.y; acc.z += a.z; acc.w += a.w;
        }
        g_parto4[(b * NCB + c) * 64 + t] = acc;
        __threadfence();                        // release (storing threads only)
    }
    __syncthreads();

    // ---- sync 2: last block of batch reduces + writes out ----
    if (t == 0) {
        __threadfence();                        // release for t0's g_partw store
        int old = atomicAdd(&g_c2[b], 1);
        s_last = (old == NCB - 1) ? 1 : 0;
    }
    __syncthreads();
    if (s_last) {
        if (t == 0) {
            __threadfence();                    // acquire
            float4 a4 = make_float4(EPSF, EPSF, EPSF, EPSF);
            #pragma unroll
            for (int i = 0; i < NCB; i++) {
                float4 q = g_partw4[b * NCB + i];
                a4.x += q.x; a4.y += q.y; a4.z += q.z; a4.w += q.w;
            }
            s_winv.x = 1.f / a4.x; s_winv.y = 1.f / a4.y;
            s_winv.z = 1.f / a4.z; s_winv.w = 1.f / a4.w;
        }
        __syncthreads();
        if (t < 64) {
            float4 r = make_float4(0.f, 0.f, 0.f, 0.f);
            #pragma unroll
            for (int i = 0; i < NCB; i++) {
                float4 a = g_parto4[(b * NCB + i) * 64 + t];
                r.x += a.x; r.y += a.y; r.z += a.z; r.w += a.w;
            }
            float inv = (t < 16) ? s_winv.x : (t < 32) ? s_winv.y
                      : (t < 48) ? s_winv.z : s_winv.w;
            r.x *= inv; r.y *= inv; r.z *= inv; r.w *= inv;
            *(((float4*)out) + b * 64 + t) = r;
        }
        if (t == 0) {                           // reset counters for next replay
            g_c1[b] = 0;
            g_c2[b] = 0;
        }
    }
}

// =====================================================================
extern "C" void kernel_launch(void* const* d_in, const int* in_sizes, int n_in,
                              void* d_out, int out_size) {
    const float* mem  = nullptr;
    const float* ctrl = nullptr;
    const float* prev = nullptr;
    for (int i = 0; i < n_in; i++) {
        if (in_sizes[i] == BB * NN * WW)     mem  = (const float*)d_in[i];
        else if (in_sizes[i] == BB * 280)    ctrl = (const float*)d_in[i];
        else if (in_sizes[i] == BB * 4 * NN) prev = (const float*)d_in[i];
    }

    dim3 grid(NCB, BB);
    k_fused<<<grid, 256>>>(mem, ctrl, prev, (float*)d_out);
}

// round 17
// speedup vs baseline: 1.3216x; 1.1547x over previous
#include <cuda_runtime.h>
#include <cstdint>

#define BB 64
#define NN 8192
#define WW 64
#define EPSF 1e-8f
#define NCB 8             // chunks (blocks) per batch
#define RB 1024           // rows per block
#define NSLAB (RB / 256)  // 4

typedef unsigned long long ull;

// ---------------- scratch (device globals; no allocation allowed) ----------------
__device__ __align__(16) float4 g_parte4[BB * NCB];        // per-chunk e sums (per head)
__device__ __align__(16) float4 g_partw4[BB * NCB];        // per-chunk w sums (per head)
__device__ __align__(16) float4 g_parto4[BB * NCB * 64];   // per-chunk output partials
__device__ __align__(16) float4 g_edge[BB][NCB][2];        // boundary e rows [first,last]
__device__ int g_c1[BB];                                   // phase-A arrival counters
__device__ int g_c2[BB];                                   // phase-C arrival counters

__device__ __forceinline__ float softplusf(float x) {
    return (x > 20.f) ? x : log1pf(expf(x));
}
__device__ __forceinline__ ull pk2(float lo, float hi) {
    ull r; asm("mov.b64 %0, {%1, %2};" : "=l"(r) : "f"(lo), "f"(hi)); return r;
}
__device__ __forceinline__ void upk2(ull v, float& lo, float& hi) {
    asm("mov.b64 {%0, %1}, %2;" : "=f"(lo), "=f"(hi) : "l"(v));
}
__device__ __forceinline__ ull ffma2(ull a, ull b, ull c) {
    ull d; asm("fma.rn.f32x2 %0, %1, %2, %3;" : "=l"(d) : "l"(a), "l"(b), "l"(c)); return d;
}

// =====================================================================
// Fused kernel (R12 base): scores -> arrive -> [prev-part overlap] -> spin
//   -> weights (smem-only) -> read -> out.
// grid (NCB, BB) = 512 blocks, 256 threads, 2 blocks/SM.
// =====================================================================
__global__ void __launch_bounds__(256, 2) k_fused(const float* __restrict__ mem,
                                                  const float* __restrict__ ctrl,
                                                  const float* __restrict__ prev,
                                                  float* __restrict__ out) {
    __shared__ float4 s_buf[RB];        // e (A/B), then w (C), then reduction  (16KB)
    __shared__ float4 s_pp[RB];         // prev-dependent shift part            (16KB)
    __shared__ float4 s_dot[256];       // per-slab dots (4KB)
    __shared__ float  s_nm[256];        // per-slab norms (1KB)
    __shared__ float  s_keys[256];
    __shared__ float  s_nk[4], s_beta[4];
    __shared__ float4 s_scA[4], s_scB[4];
    __shared__ float4 s_pw[8];
    __shared__ float4 s_einv, s_winv;
    __shared__ int    s_last;

    const int t    = threadIdx.x;
    const int lane = t & 31;
    const int wid  = t >> 5;
    const int cc   = lane & 7;          // 16B chunk id within row half
    const int rq   = lane >> 3;         // row within warp quad
    const int c    = blockIdx.x;        // chunk 0..7
    const int b    = blockIdx.y;
    const float* cb = ctrl + b * 280;

    // ---- prep: keys + per-head scalars ----
    s_keys[t] = tanhf(cb[t]);
    __syncthreads();
    if (t < 4) {
        const float* kk = s_keys + t * 64;
        float s = 0.f;
        #pragma unroll
        for (int w = 0; w < 64; w++) s = fmaf(kk[w], kk[w], s);
        s_nk[t]   = sqrtf(s);
        s_beta[t] = softplusf(cb[256 + t]);
        float gate  = 1.f / (1.f + expf(-cb[260 + t]));
        float gamma = 1.f + softplusf(cb[276 + t]);
        float a0 = cb[264 + t * 3], a1 = cb[265 + t * 3], a2 = cb[266 + t * 3];
        float mx = fmaxf(a0, fmaxf(a1, a2));
        float e0 = expf(a0 - mx), e1 = expf(a1 - mx), e2 = expf(a2 - mx);
        float inv3 = 1.f / (e0 + e1 + e2);
        s_scA[t] = make_float4(gate, gamma, 0.f, 0.f);
        s_scB[t] = make_float4(e0 * inv3, e1 * inv3, e2 * inv3, 0.f);
    }
    __syncthreads();

    // keys for chunks (j*8 + cc), j=0,1, all 4 heads -> 16 ull regs
    ull kk[4][2][2];
    #pragma unroll
    for (int h = 0; h < 4; h++)
        #pragma unroll
        for (int j = 0; j < 2; j++) {
            float4 kv = *(const float4*)(s_keys + h * 64 + j * 32 + cc * 4);
            kk[h][j][0] = pk2(kv.x, kv.y); kk[h][j][1] = pk2(kv.z, kv.w);
        }

    const float4* mem4 = (const float4*)mem + ((size_t)b * NN + (size_t)c * RB) * 16;

    // ================= Phase A: scores, e -> s_buf =================
    float4 esum = make_float4(0.f, 0.f, 0.f, 0.f);
    for (int slab = 0; slab < NSLAB; slab++) {
        #pragma unroll
        for (int it = 0; it < 8; it++) {
            const int rs = it * 32 + wid * 4 + rq;        // row within slab 0..255
            const int rl = slab * 256 + rs;
            float4 m0 = mem4[rl * 16 + cc];
            float4 m1 = mem4[rl * 16 + 8 + cc];
            ull p0 = pk2(m0.x, m0.y), p1 = pk2(m0.z, m0.w);
            ull p2 = pk2(m1.x, m1.y), p3 = pk2(m1.z, m1.w);

            ull nm = ffma2(p0, p0, 0ull); nm = ffma2(p1, p1, nm);
            nm = ffma2(p2, p2, nm);       nm = ffma2(p3, p3, nm);
            ull d0 = ffma2(p0, kk[0][0][0], 0ull); d0 = ffma2(p1, kk[0][0][1], d0);
            d0 = ffma2(p2, kk[0][1][0], d0);       d0 = ffma2(p3, kk[0][1][1], d0);
            ull d1 = ffma2(p0, kk[1][0][0], 0ull); d1 = ffma2(p1, kk[1][0][1], d1);
            d1 = ffma2(p2, kk[1][1][0], d1);       d1 = ffma2(p3, kk[1][1][1], d1);
            ull d2 = ffma2(p0, kk[2][0][0], 0ull); d2 = ffma2(p1, kk[2][0][1], d2);
            d2 = ffma2(p2, kk[2][1][0], d2);       d2 = ffma2(p3, kk[2][1][1], d2);
            ull d3 = ffma2(p0, kk[3][0][0], 0ull); d3 = ffma2(p1, kk[3][0][1], d3);
            d3 = ffma2(p2, kk[3][1][0], d3);       d3 = ffma2(p3, kk[3][1][1], d3);

            float lo, hi;
            upk2(nm, lo, hi); float vn = lo + hi;
            upk2(d0, lo, hi); float v0 = lo + hi;
            upk2(d1, lo, hi); float v1 = lo + hi;
            upk2(d2, lo, hi); float v2 = lo + hi;
            upk2(d3, lo, hi); float v3 = lo + hi;
            #pragma unroll
            for (int s = 1; s <= 4; s <<= 1) {            // 8-lane butterfly
                vn += __shfl_xor_sync(0xffffffffu, vn, s);
                v0 += __shfl_xor_sync(0xffffffffu, v0, s);
                v1 += __shfl_xor_sync(0xffffffffu, v1, s);
                v2 += __shfl_xor_sync(0xffffffffu, v2, s);
                v3 += __shfl_xor_sync(0xffffffffu, v3, s);
            }
            if (cc == 0) {
                s_dot[rs] = make_float4(v0, v1, v2, v3);
                s_nm[rs]  = vn;
            }
        }
        __syncthreads();
        {   // slab epilogue: all 256 threads, one row each (MUFU spread)
            float4 d  = s_dot[t];
            float nmr = sqrtf(s_nm[t]);
            float4 e;
            e.x = __expf(s_beta[0] * (__fdividef(d.x, nmr * s_nk[0] + EPSF) - 1.f));
            e.y = __expf(s_beta[1] * (__fdividef(d.y, nmr * s_nk[1] + EPSF) - 1.f));
            e.z = __expf(s_beta[2] * (__fdividef(d.z, nmr * s_nk[2] + EPSF) - 1.f));
            e.w = __expf(s_beta[3] * (__fdividef(d.w, nmr * s_nk[3] + EPSF) - 1.f));
            s_buf[slab * 256 + t] = e;
            esum.x += e.x; esum.y += e.y; esum.z += e.z; esum.w += e.w;
        }
        __syncthreads();
    }

    // block e-sum reduction
    #pragma unroll
    for (int s = 16; s > 0; s >>= 1) {
        esum.x += __shfl_xor_sync(0xffffffffu, esum.x, s);
        esum.y += __shfl_xor_sync(0xffffffffu, esum.y, s);
        esum.z += __shfl_xor_sync(0xffffffffu, esum.z, s);
        esum.w += __shfl_xor_sync(0xffffffffu, esum.w, s);
    }
    if (lane == 0) s_pw[wid] = esum;
    __syncthreads();

    // ---- sync 1a: publish e-sum + edges and ARRIVE (no spin yet) ----
    if (t == 0) {
        float4 a = s_pw[0];
        #pragma unroll
        for (int i = 1; i < 8; i++) {
            float4 q = s_pw[i];
            a.x += q.x; a.y += q.y; a.z += q.z; a.w += q.w;
        }
        g_parte4[b * NCB + c] = a;
        g_edge[b][c][0] = s_buf[0];
        g_edge[b][c][1] = s_buf[RB - 1];
        __threadfence();                       // release (t0 performed all these stores)
        atomicAdd(&g_c1[b], 1);
    }

    // ---- overlap: prev-dependent shift part -> s_pp (hides prev DRAM latency) ----
    {
        #pragma unroll
        for (int j = 0; j < NSLAB; j++) {
            const int r = j * 256 + t;
            const int n = c * RB + r;
            const int nmi = (n - 1) & (NN - 1);
            const int npi = (n + 1) & (NN - 1);
            float pp[4];
            #pragma unroll
            for (int h = 0; h < 4; h++) {
                float om = 1.f - s_scA[h].x;
                float4 Bv = s_scB[h];
                const float* pb = prev + ((size_t)b * 4 + h) * NN;
                pp[h] = om * (Bv.x * pb[nmi] + Bv.y * pb[n] + Bv.z * pb[npi]);
            }
            s_pp[r] = make_float4(pp[0], pp[1], pp[2], pp[3]);
        }
    }

    // ---- sync 1b: spin (usually already satisfied), compute einv ----
    if (t == 0) {
        while (*((volatile int*)&g_c1[b]) < NCB) __nanosleep(32);
        __threadfence();                       // acquire
        float4 a4 = make_float4(0.f, 0.f, 0.f, 0.f);
        #pragma unroll
        for (int i = 0; i < NCB; i++) {
            float4 p = g_parte4[b * NCB + i];
            a4.x += p.x; a4.y += p.y; a4.z += p.z; a4.w += p.w;
        }
        s_einv.x = 1.f / a4.x; s_einv.y = 1.f / a4.y;
        s_einv.z = 1.f / a4.z; s_einv.w = 1.f / a4.w;
    }
    __syncthreads();

    // ================= Phase B: weights = einv*e_lin + p_part, sharpen =================
    float4 wreg[NSLAB];
    {
        float4 wacc = make_float4(0.f, 0.f, 0.f, 0.f);
        const float4 edgeL = g_edge[b][(c + NCB - 1) & (NCB - 1)][1];
        const float4 edgeR = g_edge[b][(c + 1) & (NCB - 1)][0];
        const float4 ei4 = s_einv;
        #pragma unroll
        for (int j = 0; j < NSLAB; j++) {
            const int r = j * 256 + t;
            float4 ec = s_buf[r];
            float4 em = (r == 0)      ? edgeL : s_buf[r - 1];
            float4 ep = (r == RB - 1) ? edgeR : s_buf[r + 1];
            float4 pp = s_pp[r];
            float emv[4] = {em.x, em.y, em.z, em.w};
            float ecv[4] = {ec.x, ec.y, ec.z, ec.w};
            float epv[4] = {ep.x, ep.y, ep.z, ep.w};
            float ppv[4] = {pp.x, pp.y, pp.z, pp.w};
            float eiv[4] = {ei4.x, ei4.y, ei4.z, ei4.w};
            float ws[4];
            #pragma unroll
            for (int h = 0; h < 4; h++) {
                float4 A  = s_scA[h];
                float4 Bv = s_scB[h];
                float e_lin = A.x * (Bv.x * emv[h] + Bv.y * ecv[h] + Bv.z * epv[h]);
                float wsf = fmaf(e_lin, eiv[h], ppv[h]);
                ws[h] = __powf(wsf, A.y);       // wsf > 0 always
            }
            wreg[j] = make_float4(ws[0], ws[1], ws[2], ws[3]);
            wacc.x += ws[0]; wacc.y += ws[1]; wacc.z += ws[2]; wacc.w += ws[3];
        }
        __syncthreads();                        // all e reads done
        #pragma unroll
        for (int j = 0; j < NSLAB; j++) s_buf[j * 256 + t] = wreg[j];

        #pragma unroll
        for (int s = 16; s > 0; s >>= 1) {
            wacc.x += __shfl_xor_sync(0xffffffffu, wacc.x, s);
            wacc.y += __shfl_xor_sync(0xffffffffu, wacc.y, s);
            wacc.z += __shfl_xor_sync(0xffffffffu, wacc.z, s);
            wacc.w += __shfl_xor_sync(0xffffffffu, wacc.w, s);
        }
        if (lane == 0) s_pw[wid] = wacc;
    }
    __syncthreads();
    if (t == 0) {
        float4 a = s_pw[0];
        #pragma unroll
        for (int i = 1; i < 8; i++) {
            float4 q = s_pw[i];
            a.x += q.x; a.y += q.y; a.z += q.z; a.w += q.w;
        }
        g_partw4[b * NCB + c] = a;              // fenced before c2 add
    }

    // ================= Phase C: read pass (L2-hot), accumulate =================
    const int rsub = t >> 4;
    const int w4   = t & 15;
    const float4* basec = mem4 + w4;

    ull a00 = 0, a01 = 0, a10 = 0, a11 = 0, a20 = 0, a21 = 0, a30 = 0, a31 = 0;
    #pragma unroll 8
    for (int k = 0; k < RB / 16; k++) {
        const int r = k * 16 + rsub;
        float4 m  = basec[r * 16];
        float4 wv = s_buf[r];                   // 2-address broadcast per warp
        ull w0 = pk2(wv.x, wv.x), w1 = pk2(wv.y, wv.y);
        ull w2 = pk2(wv.z, wv.z), w3 = pk2(wv.w, wv.w);
        ull m01 = pk2(m.x, m.y), m23 = pk2(m.z, m.w);
        a00 = ffma2(w0, m01, a00); a01 = ffma2(w0, m23, a01);
        a10 = ffma2(w1, m01, a10); a11 = ffma2(w1, m23, a11);
        a20 = ffma2(w2, m01, a20); a21 = ffma2(w2, m23, a21);
        a30 = ffma2(w3, m01, a30); a31 = ffma2(w3, m23, a31);
    }

    __syncthreads();                            // w consumed; reuse s_buf as reduction buf
    {
        ulonglong2 q;
        q.x = a00; q.y = a01; *(ulonglong2*)&s_buf[(rsub * 4 + 0) * 16 + w4] = q;
        q.x = a10; q.y = a11; *(ulonglong2*)&s_buf[(rsub * 4 + 1) * 16 + w4] = q;
        q.x = a20; q.y = a21; *(ulonglong2*)&s_buf[(rsub * 4 + 2) * 16 + w4] = q;
        q.x = a30; q.y = a31; *(ulonglong2*)&s_buf[(rsub * 4 + 3) * 16 + w4] = q;
    }
    __syncthreads();
    if (t < 64) {
        const int h = t >> 4, w = t & 15;
        float4 acc = s_buf[(0 * 4 + h) * 16 + w];
        #pragma unroll
        for (int k = 1; k < 16; k++) {
            float4 a = s_buf[(k * 4 + h) * 16 + w];
            acc.x += a.x; acc.y += a.y; acc.z += a.z; acc.w += a.w;
        }
        g_parto4[(b * NCB + c) * 64 + t] = acc;
        __threadfence();                        // release (storing threads only)
    }
    __syncthreads();

    // ---- sync 2: last block of batch reduces + writes out ----
    if (t == 0) {
        __threadfence();                        // release for t0's g_partw store
        int old = atomicAdd(&g_c2[b], 1);
        s_last = (old == NCB - 1) ? 1 : 0;
    }
    __syncthreads();
    if (s_last) {
        if (t == 0) {
            __threadfence();                    // acquire
            float4 a4 = make_float4(EPSF, EPSF, EPSF, EPSF);
            #pragma unroll
            for (int i = 0; i < NCB; i++) {
                float4 q = g_partw4[b * NCB + i];
                a4.x += q.x; a4.y += q.y; a4.z += q.z; a4.w += q.w;
            }
            s_winv.x = 1.f / a4.x; s_winv.y = 1.f / a4.y;
            s_winv.z = 1.f / a4.z; s_winv.w = 1.f / a4.w;
        }
        __syncthreads();
        if (t < 64) {
            float4 r = make_float4(0.f, 0.f, 0.f, 0.f);
            #pragma unroll
            for (int i = 0; i < NCB; i++) {
                float4 a = g_parto4[(b * NCB + i) * 64 + t];
                r.x += a.x; r.y += a.y; r.z += a.z; r.w += a.w;
            }
            float inv = (t < 16) ? s_winv.x : (t < 32) ? s_winv.y
                      : (t < 48) ? s_winv.z : s_winv.w;
            r.x *= inv; r.y *= inv; r.z *= inv; r.w *= inv;
            *(((float4*)out) + b * 64 + t) = r;
        }
        if (t == 0) {                           // reset counters for next replay
            g_c1[b] = 0;
            g_c2[b] = 0;
        }
    }
}

// =====================================================================
extern "C" void kernel_launch(void* const* d_in, const int* in_sizes, int n_in,
                              void* d_out, int out_size) {
    const float* mem  = nullptr;
    const float* ctrl = nullptr;
    const float* prev = nullptr;
    for (int i = 0; i < n_in; i++) {
        if (in_sizes[i] == BB * NN * WW)     mem  = (const float*)d_in[i];
        else if (in_sizes[i] == BB * 280)    ctrl = (const float*)d_in[i];
        else if (in_sizes[i] == BB * 4 * NN) prev = (const float*)d_in[i];
    }

    dim3 grid(NCB, BB);
    k_fused<<<grid, 256>>>(mem, ctrl, prev, (float*)d_out);
}